// round 2
// baseline (speedup 1.0000x reference)
#include <cuda_runtime.h>
#include <math.h>
#include <float.h>

// Problem constants
#define M_ROWS 16384
#define INDIM  1024
#define H1D    1024
#define H2D    512
#define H3D    256
#define LATD   256
#define DDIM   32
#define KCODES 2048
#define NROWS  (M_ROWS * LATD / DDIM)   // 131072 VQ rows

// Output layout (floats): z | e | recon | loss, recon_loss, vq_loss
#define Z_OFF   0
#define E_OFF   (M_ROWS * LATD)                 // 4194304
#define R_OFF   (E_OFF + M_ROWS * LATD)         // 8388608
#define SC_OFF  (R_OFF + M_ROWS * INDIM)        // 25165824

// Scratch activations (static device globals; no runtime allocation)
__device__ float g_h1[M_ROWS * H1D];   // 64 MB
__device__ float g_h2[M_ROWS * H2D];   // 32 MB
__device__ float g_h3[M_ROWS * H3D];   // 16 MB
__device__ float g_vq_part[512];
__device__ float g_rec_part[512];

// ----------------------------------------------------------------------------
// Tiled fp32 GEMM: C[M,N] = act(A[M,K] @ W[K,N] + bias[N])
// BM=BN=128, BK=8, 256 threads, 8x8 per thread, register prefetch of next tile.
// ACT: 0=none, 1=leaky(0.01), 2=sigmoid
// ----------------------------------------------------------------------------
template <int ACT>
__global__ __launch_bounds__(256) void gemm_bias_act(
    const float* __restrict__ A, const float* __restrict__ W,
    const float* __restrict__ bias, float* __restrict__ C,
    int M, int N, int K)
{
    __shared__ __align__(16) float As[8][128];
    __shared__ __align__(16) float Bs[8][128];

    const int t  = threadIdx.x;
    const int tx = t & 15;          // 0..15 -> col group
    const int ty = t >> 4;          // 0..15 -> row group
    const int bx = blockIdx.x;      // N tile
    const int by = blockIdx.y;      // M tile

    // A tile load mapping: 128 rows x 8 cols = 256 float4 (1 per thread)
    const int a_row = t >> 1;               // 0..127
    const int a_vec = (t & 1) * 4;          // 0 or 4
    const float* Ap = A + (size_t)(by * 128 + a_row) * K + a_vec;

    // B tile load mapping: 8 rows x 128 cols = 256 float4 (1 per thread)
    const int b_row = t >> 5;               // 0..7
    const int b_col = (t & 31) * 4;         // 0..124
    const float* Wp = W + (size_t)b_row * N + bx * 128 + b_col;

    float acc[8][8];
#pragma unroll
    for (int i = 0; i < 8; i++)
#pragma unroll
        for (int j = 0; j < 8; j++) acc[i][j] = 0.f;

    float4 aF = *(const float4*)Ap;
    float4 bF = *(const float4*)Wp;

    for (int kt = 0; kt < K; kt += 8) {
        // stage current tile to smem
        As[a_vec + 0][a_row] = aF.x;
        As[a_vec + 1][a_row] = aF.y;
        As[a_vec + 2][a_row] = aF.z;
        As[a_vec + 3][a_row] = aF.w;
        *(float4*)&Bs[b_row][b_col] = bF;
        __syncthreads();

        // prefetch next tile into registers
        if (kt + 8 < K) {
            Ap += 8;
            Wp += (size_t)8 * N;
            aF = *(const float4*)Ap;
            bF = *(const float4*)Wp;
        }

#pragma unroll
        for (int k = 0; k < 8; k++) {
            float4 a0 = *(const float4*)&As[k][ty * 8];
            float4 a1 = *(const float4*)&As[k][ty * 8 + 4];
            float4 b0 = *(const float4*)&Bs[k][tx * 8];
            float4 b1 = *(const float4*)&Bs[k][tx * 8 + 4];
            float av[8] = {a0.x, a0.y, a0.z, a0.w, a1.x, a1.y, a1.z, a1.w};
            float bv[8] = {b0.x, b0.y, b0.z, b0.w, b1.x, b1.y, b1.z, b1.w};
#pragma unroll
            for (int i = 0; i < 8; i++)
#pragma unroll
                for (int j = 0; j < 8; j++)
                    acc[i][j] = fmaf(av[i], bv[j], acc[i][j]);
        }
        __syncthreads();
    }

    // epilogue: bias + activation + store
    const int colBase = bx * 128 + tx * 8;
    float4 bb0 = *(const float4*)&bias[colBase];
    float4 bb1 = *(const float4*)&bias[colBase + 4];
    float bv[8] = {bb0.x, bb0.y, bb0.z, bb0.w, bb1.x, bb1.y, bb1.z, bb1.w};

#pragma unroll
    for (int i = 0; i < 8; i++) {
        const int row = by * 128 + ty * 8 + i;
        float v[8];
#pragma unroll
        for (int j = 0; j < 8; j++) {
            float x = acc[i][j] + bv[j];
            if (ACT == 1) x = (x > 0.f) ? x : 0.01f * x;
            else if (ACT == 2) x = 1.f / (1.f + expf(-x));
            v[j] = x;
        }
        float* Cp = C + (size_t)row * N + colBase;
        *(float4*)(Cp)     = make_float4(v[0], v[1], v[2], v[3]);
        *(float4*)(Cp + 4) = make_float4(v[4], v[5], v[6], v[7]);
    }
}

// ----------------------------------------------------------------------------
// Vector quantizer. Distance computed EXACTLY like the reference:
//   d = (||z||^2 + ||E_k||^2) - 2 * (z . E_k)      [all fp32, same association]
// The ||z||^2 term dominates (~O(10)) so fp32 rounds distances onto a coarse
// (~1e-6) grid; including it with the same association reproduces the
// reference's tie structure, and strict '<' matches argmin's first-index rule.
// Grid: 512 blocks x 256 threads, 1 row per thread (131072 rows).
// ----------------------------------------------------------------------------
#define VQ_CHUNK 256
__global__ __launch_bounds__(256) void vq_kernel(
    const float* __restrict__ z, const float* __restrict__ E,
    float* __restrict__ q_out, float* __restrict__ part)
{
    __shared__ __align__(16) float sE[VQ_CHUNK * DDIM];   // 32 KB
    __shared__ float sEn[VQ_CHUNK];
    __shared__ float sred[256];

    const int t = threadIdx.x;
    const size_t row = (size_t)blockIdx.x * 256 + t;

    // load this thread's z row into registers
    float4 zv[8];
    const float4* zp = (const float4*)(z + row * DDIM);
#pragma unroll
    for (int i = 0; i < 8; i++) zv[i] = zp[i];

    // ||z||^2 in plain fp32 sequential order (like jnp.sum(zr*zr))
    float zz = 0.f;
#pragma unroll
    for (int i = 0; i < 8; i++) {
        zz += zv[i].x * zv[i].x;
        zz += zv[i].y * zv[i].y;
        zz += zv[i].z * zv[i].z;
        zz += zv[i].w * zv[i].w;
    }

    float best = FLT_MAX;
    int bidx = 0;

    for (int c0 = 0; c0 < KCODES; c0 += VQ_CHUNK) {
        __syncthreads();
        // stage E chunk (256 codes x 32 floats = 2048 float4, 8 per thread)
        const float4* Ep = (const float4*)(E + (size_t)c0 * DDIM);
        float4* sEp = (float4*)sE;
#pragma unroll
        for (int i = 0; i < 8; i++) sEp[t + i * 256] = Ep[t + i * 256];
        __syncthreads();
        // code norms (1 per thread), plain fp32 sequential sum
        {
            const float* e1 = sE + t * DDIM;
            float s = 0.f;
#pragma unroll
            for (int j = 0; j < DDIM; j++) s += e1[j] * e1[j];
            sEn[t] = s;
        }
        __syncthreads();

        for (int c = 0; c < VQ_CHUNK; c++) {
            const float4* e4 = (const float4*)(sE + c * DDIM);
            float dot = 0.f;
#pragma unroll
            for (int j = 0; j < 8; j++) {
                float4 ev = e4[j];
                dot = fmaf(zv[j].x, ev.x, dot);
                dot = fmaf(zv[j].y, ev.y, dot);
                dot = fmaf(zv[j].z, ev.z, dot);
                dot = fmaf(zv[j].w, ev.w, dot);
            }
            // reference association: (zz + En) - 2*dot, all fp32
            float d = (zz + sEn[c]) - 2.f * dot;
            if (d < best) { best = d; bidx = c0 + c; }  // strict < == argmin first-index
        }
    }

    // gather q and accumulate ||q - z||^2
    const float4* eq = (const float4*)(E + (size_t)bidx * DDIM);
    float4* qo = (float4*)(q_out + row * DDIM);
    float s = 0.f;
#pragma unroll
    for (int j = 0; j < 8; j++) {
        float4 v = eq[j];
        qo[j] = v;
        float dx = v.x - zv[j].x, dy = v.y - zv[j].y;
        float dz = v.z - zv[j].z, dw = v.w - zv[j].w;
        s += dx * dx + dy * dy + dz * dz + dw * dw;
    }

    sred[t] = s;
    __syncthreads();
    for (int o = 128; o > 0; o >>= 1) {
        if (t < o) sred[t] += sred[t + o];
        __syncthreads();
    }
    if (t == 0) part[blockIdx.x] = sred[0];
}

// ----------------------------------------------------------------------------
// recon loss partials: sum (recon - x)^2 over 16384*1024 elements
// ----------------------------------------------------------------------------
__global__ __launch_bounds__(256) void recon_loss_kernel(
    const float* __restrict__ recon, const float* __restrict__ x,
    float* __restrict__ part)
{
    __shared__ float sred[256];
    const int t = threadIdx.x;
    const float4* r4 = (const float4*)recon;
    const float4* x4 = (const float4*)x;
    const size_t n4 = (size_t)M_ROWS * INDIM / 4;   // 4194304
    float s = 0.f;
    for (size_t i = (size_t)blockIdx.x * 256 + t; i < n4; i += (size_t)gridDim.x * 256) {
        float4 r = r4[i], xx = x4[i];
        float dx = r.x - xx.x, dy = r.y - xx.y, dz = r.z - xx.z, dw = r.w - xx.w;
        s += dx * dx + dy * dy + dz * dz + dw * dw;
    }
    sred[t] = s;
    __syncthreads();
    for (int o = 128; o > 0; o >>= 1) {
        if (t < o) sred[t] += sred[t + o];
        __syncthreads();
    }
    if (t == 0) part[blockIdx.x] = sred[0];
}

// ----------------------------------------------------------------------------
// finalize: reduce partials, write {loss, recon_loss, vq_loss}
// vq_loss = (1 + BETA) * mean_b ||q - z||^2  (commit == embed numerically)
// ----------------------------------------------------------------------------
__global__ __launch_bounds__(512) void finalize_kernel(
    const float* __restrict__ vqp, const float* __restrict__ recp,
    float* __restrict__ out_sc)
{
    __shared__ float sv[512];
    __shared__ float sr[512];
    const int t = threadIdx.x;
    sv[t] = vqp[t];
    sr[t] = recp[t];
    __syncthreads();
    for (int o = 256; o > 0; o >>= 1) {
        if (t < o) { sv[t] += sv[t + o]; sr[t] += sr[t + o]; }
        __syncthreads();
    }
    if (t == 0) {
        float vq_loss = 1.25f * sv[0] / (float)M_ROWS;
        float rec_loss = sr[0] / (float)M_ROWS;
        out_sc[0] = rec_loss + vq_loss;  // loss
        out_sc[1] = rec_loss;            // recon_loss
        out_sc[2] = vq_loss;             // vq_loss
    }
}

// ----------------------------------------------------------------------------
extern "C" void kernel_launch(void* const* d_in, const int* in_sizes, int n_in,
                              void* d_out, int out_size)
{
    const float* x   = (const float*)d_in[0];
    const float* We1 = (const float*)d_in[1];
    const float* be1 = (const float*)d_in[2];
    const float* We2 = (const float*)d_in[3];
    const float* be2 = (const float*)d_in[4];
    const float* We3 = (const float*)d_in[5];
    const float* be3 = (const float*)d_in[6];
    const float* We4 = (const float*)d_in[7];
    const float* be4 = (const float*)d_in[8];
    const float* E   = (const float*)d_in[9];
    const float* Wd1 = (const float*)d_in[10];
    const float* bd1 = (const float*)d_in[11];
    const float* Wd2 = (const float*)d_in[12];
    const float* bd2 = (const float*)d_in[13];
    const float* Wd3 = (const float*)d_in[14];
    const float* bd3 = (const float*)d_in[15];
    const float* Wd4 = (const float*)d_in[16];
    const float* bd4 = (const float*)d_in[17];

    float* out   = (float*)d_out;
    float* z     = out + Z_OFF;
    float* e     = out + E_OFF;
    float* recon = out + R_OFF;

    float *h1, *h2, *h3, *vqp, *recp;
    cudaGetSymbolAddress((void**)&h1,   g_h1);
    cudaGetSymbolAddress((void**)&h2,   g_h2);
    cudaGetSymbolAddress((void**)&h3,   g_h3);
    cudaGetSymbolAddress((void**)&vqp,  g_vq_part);
    cudaGetSymbolAddress((void**)&recp, g_rec_part);

    const dim3 blk(256);

    // encoder
    gemm_bias_act<1><<<dim3(H1D/128, 128), blk>>>(x,  We1, be1, h1, M_ROWS, H1D, INDIM);
    gemm_bias_act<1><<<dim3(H2D/128, 128), blk>>>(h1, We2, be2, h2, M_ROWS, H2D, H1D);
    gemm_bias_act<1><<<dim3(H3D/128, 128), blk>>>(h2, We3, be3, h3, M_ROWS, H3D, H2D);
    gemm_bias_act<0><<<dim3(LATD/128, 128), blk>>>(h3, We4, be4, z,  M_ROWS, LATD, H3D);

    // vector quantizer (writes e = q, vq partials)
    vq_kernel<<<512, 256>>>(z, E, e, vqp);

    // decoder
    gemm_bias_act<1><<<dim3(H3D/128, 128), blk>>>(e,  Wd1, bd1, h3, M_ROWS, H3D, LATD);
    gemm_bias_act<1><<<dim3(H2D/128, 128), blk>>>(h3, Wd2, bd2, h2, M_ROWS, H2D, H3D);
    gemm_bias_act<1><<<dim3(H1D/128, 128), blk>>>(h2, Wd3, bd3, h1, M_ROWS, H1D, H2D);
    gemm_bias_act<2><<<dim3(INDIM/128, 128), blk>>>(h1, Wd4, bd4, recon, M_ROWS, INDIM, H1D);

    // losses
    recon_loss_kernel<<<512, 256>>>(recon, x, recp);
    finalize_kernel<<<1, 512>>>(vqp, recp, out + SC_OFF);
}

// round 4
// speedup vs baseline: 1.1361x; 1.1361x over previous
#include <cuda_runtime.h>
#include <math.h>
#include <float.h>
#include <stdint.h>

// Problem constants
#define M_ROWS 16384
#define INDIM  1024
#define H1D    1024
#define H2D    512
#define H3D    256
#define LATD   256
#define DDIM   32
#define KCODES 2048

// Output layout (floats): z | e | recon | loss, recon_loss, vq_loss
#define Z_OFF   0
#define E_OFF   (M_ROWS * LATD)
#define R_OFF   (E_OFF + M_ROWS * LATD)
#define SC_OFF  (R_OFF + M_ROWS * INDIM)

// Scratch (static device globals)
__device__ float g_h1[M_ROWS * H1D];
__device__ float g_h2[M_ROWS * H2D];
__device__ float g_h3[M_ROWS * H3D];
__device__ float g_vq_part[512];
__device__ float g_rec_part[512];
// transposed decoder weights: Wt[n,k] = W[k,n]
#define WT1_OFF 0                         // [256 x 256]
#define WT2_OFF (WT1_OFF + 256*256)       // [512 x 256]
#define WT3_OFF (WT2_OFF + 512*256)      // [1024 x 512]
#define WT4_OFF (WT3_OFF + 1024*512)      // [1024 x 1024]
__device__ float g_wt[WT4_OFF + 1024*1024];

// ============================================================================
// tf32 helpers
// ============================================================================
__device__ __forceinline__ float tf32_hi(float x) {
    return __uint_as_float(__float_as_uint(x) & 0xFFFFE000u);
}
// hi is an exact tf32 value; lo = x - hi (exact), masked again to tf32.
__device__ __forceinline__ void split2(float x, float& hi, float& lo) {
    hi = tf32_hi(x);
    lo = tf32_hi(x - hi);
}

__device__ __forceinline__ void mma_m16n8k8(
    float* c, uint32_t a0, uint32_t a1, uint32_t a2, uint32_t a3,
    uint32_t b0, uint32_t b1)
{
    asm volatile(
        "mma.sync.aligned.m16n8k8.row.col.f32.tf32.tf32.f32 "
        "{%0,%1,%2,%3}, {%4,%5,%6,%7}, {%8,%9}, {%0,%1,%2,%3};"
        : "+f"(c[0]), "+f"(c[1]), "+f"(c[2]), "+f"(c[3])
        : "r"(a0), "r"(a1), "r"(a2), "r"(a3), "r"(b0), "r"(b1));
}

// ============================================================================
// mma.sync 3xTF32 GEMM: C[M,N] = act(A[M,K] @ Bt[N,K]^T + bias)
// 128x128 CTA tile, 8 warps (2m x 4n), warp tile 64x32, BK=16.
// smem tiles [128][20]: 80B row stride (16B-aligned float4 stores) and
// conflict-free fragment loads (banks 20r+c distinct mod 32 for r<8).
// ACT: 0=none, 1=leaky(0.01), 2=sigmoid
// ============================================================================
#define SLD 20
template <int ACT>
__global__ __launch_bounds__(256) void gemm_tf32_mma(
    const float* __restrict__ A, const float* __restrict__ Bt,
    const float* __restrict__ bias, float* __restrict__ C,
    int M, int N, int K)
{
    __shared__ __align__(16) float sAhi[128 * SLD];
    __shared__ __align__(16) float sAlo[128 * SLD];
    __shared__ __align__(16) float sBhi[128 * SLD];
    __shared__ __align__(16) float sBlo[128 * SLD];

    const int t    = threadIdx.x;
    const int lane = t & 31;
    const int wid  = t >> 5;
    const int wm   = wid & 1;       // 0..1 -> 64-row half
    const int wn   = wid >> 1;      // 0..3 -> 32-col slice
    const int g    = lane >> 2;     // group id 0..7
    const int tg   = lane & 3;      // thread-in-group 0..3
    const int bx   = blockIdx.x;    // N tile
    const int by   = blockIdx.y;    // M tile

    float acc[4][4][4];
#pragma unroll
    for (int i = 0; i < 4; i++)
#pragma unroll
        for (int j = 0; j < 4; j++)
#pragma unroll
            for (int k = 0; k < 4; k++) acc[i][j][k] = 0.f;

    const float* Ab = A  + (size_t)(by * 128) * K;
    const float* Bb = Bt + (size_t)(bx * 128) * K;

    // tile-load mapping: 512 float4 per tile, 2 per thread
    const int r0l = t >> 2;                 // rows t/4 and t/4+64
    const int c4l = (t & 3) * 4;

    for (int kt = 0; kt < K; kt += 16) {
        __syncthreads();
#pragma unroll
        for (int i = 0; i < 2; i++) {
            const int r = r0l + i * 64;
            float4 va = *(const float4*)(Ab + (size_t)r * K + kt + c4l);
            float4 vb = *(const float4*)(Bb + (size_t)r * K + kt + c4l);
            float4 h, l;
            split2(va.x, h.x, l.x); split2(va.y, h.y, l.y);
            split2(va.z, h.z, l.z); split2(va.w, h.w, l.w);
            *(float4*)&sAhi[r * SLD + c4l] = h;
            *(float4*)&sAlo[r * SLD + c4l] = l;
            split2(vb.x, h.x, l.x); split2(vb.y, h.y, l.y);
            split2(vb.z, h.z, l.z); split2(vb.w, h.w, l.w);
            *(float4*)&sBhi[r * SLD + c4l] = h;
            *(float4*)&sBlo[r * SLD + c4l] = l;
        }
        __syncthreads();

#pragma unroll
        for (int kk = 0; kk < 16; kk += 8) {
            // A fragments (4 m-frags x 4 regs), hi and lo
            uint32_t ah[4][4], al[4][4];
            const int abase = (wm * 64 + g) * SLD + kk + tg;
#pragma unroll
            for (int mf = 0; mf < 4; mf++) {
                const int o = abase + mf * 16 * SLD;
                ah[mf][0] = __float_as_uint(sAhi[o]);
                ah[mf][1] = __float_as_uint(sAhi[o + 8 * SLD]);
                ah[mf][2] = __float_as_uint(sAhi[o + 4]);
                ah[mf][3] = __float_as_uint(sAhi[o + 8 * SLD + 4]);
                al[mf][0] = __float_as_uint(sAlo[o]);
                al[mf][1] = __float_as_uint(sAlo[o + 8 * SLD]);
                al[mf][2] = __float_as_uint(sAlo[o + 4]);
                al[mf][3] = __float_as_uint(sAlo[o + 8 * SLD + 4]);
            }
            // B fragments (4 n-frags x 2 regs), hi and lo
            uint32_t bh[4][2], bl[4][2];
            const int bbase = (wn * 32 + g) * SLD + kk + tg;
#pragma unroll
            for (int nf = 0; nf < 4; nf++) {
                const int o = bbase + nf * 8 * SLD;
                bh[nf][0] = __float_as_uint(sBhi[o]);
                bh[nf][1] = __float_as_uint(sBhi[o + 4]);
                bl[nf][0] = __float_as_uint(sBlo[o]);
                bl[nf][1] = __float_as_uint(sBlo[o + 4]);
            }
            // pass 1: hi*hi
#pragma unroll
            for (int mf = 0; mf < 4; mf++)
#pragma unroll
                for (int nf = 0; nf < 4; nf++)
                    mma_m16n8k8(acc[mf][nf], ah[mf][0], ah[mf][1], ah[mf][2], ah[mf][3],
                                bh[nf][0], bh[nf][1]);
            // pass 2: hi*lo
#pragma unroll
            for (int mf = 0; mf < 4; mf++)
#pragma unroll
                for (int nf = 0; nf < 4; nf++)
                    mma_m16n8k8(acc[mf][nf], ah[mf][0], ah[mf][1], ah[mf][2], ah[mf][3],
                                bl[nf][0], bl[nf][1]);
            // pass 3: lo*hi
#pragma unroll
            for (int mf = 0; mf < 4; mf++)
#pragma unroll
                for (int nf = 0; nf < 4; nf++)
                    mma_m16n8k8(acc[mf][nf], al[mf][0], al[mf][1], al[mf][2], al[mf][3],
                                bh[nf][0], bh[nf][1]);
        }
    }

    // epilogue: bias + act + direct float2 stores
    const int rbase = by * 128 + wm * 64 + g;
    const int cbase = bx * 128 + wn * 32 + 2 * tg;
#pragma unroll
    for (int nf = 0; nf < 4; nf++) {
        const int c0 = cbase + nf * 8;
        const float b0 = bias[c0], b1 = bias[c0 + 1];
#pragma unroll
        for (int mf = 0; mf < 4; mf++) {
            const int r = rbase + mf * 16;
            float v0 = acc[mf][nf][0] + b0;
            float v1 = acc[mf][nf][1] + b1;
            float v2 = acc[mf][nf][2] + b0;
            float v3 = acc[mf][nf][3] + b1;
            if (ACT == 1) {
                v0 = (v0 > 0.f) ? v0 : 0.01f * v0;
                v1 = (v1 > 0.f) ? v1 : 0.01f * v1;
                v2 = (v2 > 0.f) ? v2 : 0.01f * v2;
                v3 = (v3 > 0.f) ? v3 : 0.01f * v3;
            } else if (ACT == 2) {
                v0 = 1.f / (1.f + expf(-v0));
                v1 = 1.f / (1.f + expf(-v1));
                v2 = 1.f / (1.f + expf(-v2));
                v3 = 1.f / (1.f + expf(-v3));
            }
            *(float2*)(C + (size_t)r * N + c0)       = make_float2(v0, v1);
            *(float2*)(C + (size_t)(r + 8) * N + c0) = make_float2(v2, v3);
        }
    }
}

// ============================================================================
// Weight transpose: Wt[N,K] = W[K,N]  (dims % 32 == 0)
// ============================================================================
__global__ void transpose_kernel(const float* __restrict__ in, float* __restrict__ out,
                                 int K, int N)
{
    __shared__ float tile[32][33];
    const int x  = blockIdx.x * 32 + threadIdx.x;  // N index
    const int y0 = blockIdx.y * 32;                // K base
    for (int j = threadIdx.y; j < 32; j += 8)
        tile[j][threadIdx.x] = in[(size_t)(y0 + j) * N + x];
    __syncthreads();
    const int xo  = y0 + threadIdx.x;
    const int yo0 = blockIdx.x * 32;
    for (int j = threadIdx.y; j < 32; j += 8)
        out[(size_t)(yo0 + j) * K + xo] = tile[threadIdx.x][j];
}

// ============================================================================
// Encoder fp32 SIMT GEMM (unchanged — z precision is load-bearing for VQ)
// ============================================================================
template <int ACT>
__global__ __launch_bounds__(256) void gemm_bias_act(
    const float* __restrict__ A, const float* __restrict__ W,
    const float* __restrict__ bias, float* __restrict__ C,
    int M, int N, int K)
{
    __shared__ __align__(16) float As[8][128];
    __shared__ __align__(16) float Bs[8][128];

    const int t  = threadIdx.x;
    const int tx = t & 15;
    const int ty = t >> 4;
    const int bx = blockIdx.x;
    const int by = blockIdx.y;

    const int a_row = t >> 1;
    const int a_vec = (t & 1) * 4;
    const float* Ap = A + (size_t)(by * 128 + a_row) * K + a_vec;

    const int b_row = t >> 5;
    const int b_col = (t & 31) * 4;
    const float* Wp = W + (size_t)b_row * N + bx * 128 + b_col;

    float acc[8][8];
#pragma unroll
    for (int i = 0; i < 8; i++)
#pragma unroll
        for (int j = 0; j < 8; j++) acc[i][j] = 0.f;

    float4 aF = *(const float4*)Ap;
    float4 bF = *(const float4*)Wp;

    for (int kt = 0; kt < K; kt += 8) {
        As[a_vec + 0][a_row] = aF.x;
        As[a_vec + 1][a_row] = aF.y;
        As[a_vec + 2][a_row] = aF.z;
        As[a_vec + 3][a_row] = aF.w;
        *(float4*)&Bs[b_row][b_col] = bF;
        __syncthreads();

        if (kt + 8 < K) {
            Ap += 8;
            Wp += (size_t)8 * N;
            aF = *(const float4*)Ap;
            bF = *(const float4*)Wp;
        }

#pragma unroll
        for (int k = 0; k < 8; k++) {
            float4 a0 = *(const float4*)&As[k][ty * 8];
            float4 a1 = *(const float4*)&As[k][ty * 8 + 4];
            float4 b0 = *(const float4*)&Bs[k][tx * 8];
            float4 b1 = *(const float4*)&Bs[k][tx * 8 + 4];
            float av[8] = {a0.x, a0.y, a0.z, a0.w, a1.x, a1.y, a1.z, a1.w};
            float bv[8] = {b0.x, b0.y, b0.z, b0.w, b1.x, b1.y, b1.z, b1.w};
#pragma unroll
            for (int i = 0; i < 8; i++)
#pragma unroll
                for (int j = 0; j < 8; j++)
                    acc[i][j] = fmaf(av[i], bv[j], acc[i][j]);
        }
        __syncthreads();
    }

    const int colBase = bx * 128 + tx * 8;
    float4 bb0 = *(const float4*)&bias[colBase];
    float4 bb1 = *(const float4*)&bias[colBase + 4];
    float bv[8] = {bb0.x, bb0.y, bb0.z, bb0.w, bb1.x, bb1.y, bb1.z, bb1.w};

#pragma unroll
    for (int i = 0; i < 8; i++) {
        const int row = by * 128 + ty * 8 + i;
        float v[8];
#pragma unroll
        for (int j = 0; j < 8; j++) {
            float x = acc[i][j] + bv[j];
            if (ACT == 1) x = (x > 0.f) ? x : 0.01f * x;
            else if (ACT == 2) x = 1.f / (1.f + expf(-x));
            v[j] = x;
        }
        float* Cp = C + (size_t)row * N + colBase;
        *(float4*)(Cp)     = make_float4(v[0], v[1], v[2], v[3]);
        *(float4*)(Cp + 4) = make_float4(v[4], v[5], v[6], v[7]);
    }
}

// ============================================================================
// Vector quantizer (reference-matching association; unchanged)
// ============================================================================
#define VQ_CHUNK 256
__global__ __launch_bounds__(256) void vq_kernel(
    const float* __restrict__ z, const float* __restrict__ E,
    float* __restrict__ q_out, float* __restrict__ part)
{
    __shared__ __align__(16) float sE[VQ_CHUNK * DDIM];
    __shared__ float sEn[VQ_CHUNK];
    __shared__ float sred[256];

    const int t = threadIdx.x;
    const size_t row = (size_t)blockIdx.x * 256 + t;

    float4 zv[8];
    const float4* zp = (const float4*)(z + row * DDIM);
#pragma unroll
    for (int i = 0; i < 8; i++) zv[i] = zp[i];

    float zz = 0.f;
#pragma unroll
    for (int i = 0; i < 8; i++) {
        zz += zv[i].x * zv[i].x;
        zz += zv[i].y * zv[i].y;
        zz += zv[i].z * zv[i].z;
        zz += zv[i].w * zv[i].w;
    }

    float best = FLT_MAX;
    int bidx = 0;

    for (int c0 = 0; c0 < KCODES; c0 += VQ_CHUNK) {
        __syncthreads();
        const float4* Ep = (const float4*)(E + (size_t)c0 * DDIM);
        float4* sEp = (float4*)sE;
#pragma unroll
        for (int i = 0; i < 8; i++) sEp[t + i * 256] = Ep[t + i * 256];
        __syncthreads();
        {
            const float* e1 = sE + t * DDIM;
            float s = 0.f;
#pragma unroll
            for (int j = 0; j < DDIM; j++) s += e1[j] * e1[j];
            sEn[t] = s;
        }
        __syncthreads();

        for (int c = 0; c < VQ_CHUNK; c++) {
            const float4* e4 = (const float4*)(sE + c * DDIM);
            float dot = 0.f;
#pragma unroll
            for (int j = 0; j < 8; j++) {
                float4 ev = e4[j];
                dot = fmaf(zv[j].x, ev.x, dot);
                dot = fmaf(zv[j].y, ev.y, dot);
                dot = fmaf(zv[j].z, ev.z, dot);
                dot = fmaf(zv[j].w, ev.w, dot);
            }
            float d = (zz + sEn[c]) - 2.f * dot;
            if (d < best) { best = d; bidx = c0 + c; }
        }
    }

    const float4* eq = (const float4*)(E + (size_t)bidx * DDIM);
    float4* qo = (float4*)(q_out + row * DDIM);
    float s = 0.f;
#pragma unroll
    for (int j = 0; j < 8; j++) {
        float4 v = eq[j];
        qo[j] = v;
        float dx = v.x - zv[j].x, dy = v.y - zv[j].y;
        float dz = v.z - zv[j].z, dw = v.w - zv[j].w;
        s += dx * dx + dy * dy + dz * dz + dw * dw;
    }

    sred[t] = s;
    __syncthreads();
    for (int o = 128; o > 0; o >>= 1) {
        if (t < o) sred[t] += sred[t + o];
        __syncthreads();
    }
    if (t == 0) part[blockIdx.x] = sred[0];
}

// ============================================================================
// Losses
// ============================================================================
__global__ __launch_bounds__(256) void recon_loss_kernel(
    const float* __restrict__ recon, const float* __restrict__ x,
    float* __restrict__ part)
{
    __shared__ float sred[256];
    const int t = threadIdx.x;
    const float4* r4 = (const float4*)recon;
    const float4* x4 = (const float4*)x;
    const size_t n4 = (size_t)M_ROWS * INDIM / 4;
    float s = 0.f;
    for (size_t i = (size_t)blockIdx.x * 256 + t; i < n4; i += (size_t)gridDim.x * 256) {
        float4 r = r4[i], xx = x4[i];
        float dx = r.x - xx.x, dy = r.y - xx.y, dz = r.z - xx.z, dw = r.w - xx.w;
        s += dx * dx + dy * dy + dz * dz + dw * dw;
    }
    sred[t] = s;
    __syncthreads();
    for (int o = 128; o > 0; o >>= 1) {
        if (t < o) sred[t] += sred[t + o];
        __syncthreads();
    }
    if (t == 0) part[blockIdx.x] = sred[0];
}

__global__ __launch_bounds__(512) void finalize_kernel(
    const float* __restrict__ vqp, const float* __restrict__ recp,
    float* __restrict__ out_sc)
{
    __shared__ float sv[512];
    __shared__ float sr[512];
    const int t = threadIdx.x;
    sv[t] = vqp[t];
    sr[t] = recp[t];
    __syncthreads();
    for (int o = 256; o > 0; o >>= 1) {
        if (t < o) { sv[t] += sv[t + o]; sr[t] += sr[t + o]; }
        __syncthreads();
    }
    if (t == 0) {
        float vq_loss = 1.25f * sv[0] / (float)M_ROWS;
        float rec_loss = sr[0] / (float)M_ROWS;
        out_sc[0] = rec_loss + vq_loss;
        out_sc[1] = rec_loss;
        out_sc[2] = vq_loss;
    }
}

// ============================================================================
extern "C" void kernel_launch(void* const* d_in, const int* in_sizes, int n_in,
                              void* d_out, int out_size)
{
    const float* x   = (const float*)d_in[0];
    const float* We1 = (const float*)d_in[1];
    const float* be1 = (const float*)d_in[2];
    const float* We2 = (const float*)d_in[3];
    const float* be2 = (const float*)d_in[4];
    const float* We3 = (const float*)d_in[5];
    const float* be3 = (const float*)d_in[6];
    const float* We4 = (const float*)d_in[7];
    const float* be4 = (const float*)d_in[8];
    const float* E   = (const float*)d_in[9];
    const float* Wd1 = (const float*)d_in[10];
    const float* bd1 = (const float*)d_in[11];
    const float* Wd2 = (const float*)d_in[12];
    const float* bd2 = (const float*)d_in[13];
    const float* Wd3 = (const float*)d_in[14];
    const float* bd3 = (const float*)d_in[15];
    const float* Wd4 = (const float*)d_in[16];
    const float* bd4 = (const float*)d_in[17];

    float* out   = (float*)d_out;
    float* z     = out + Z_OFF;
    float* e     = out + E_OFF;
    float* recon = out + R_OFF;

    float *h1, *h2, *h3, *vqp, *recp, *wt;
    cudaGetSymbolAddress((void**)&h1,   g_h1);
    cudaGetSymbolAddress((void**)&h2,   g_h2);
    cudaGetSymbolAddress((void**)&h3,   g_h3);
    cudaGetSymbolAddress((void**)&vqp,  g_vq_part);
    cudaGetSymbolAddress((void**)&recp, g_rec_part);
    cudaGetSymbolAddress((void**)&wt,   g_wt);

    const dim3 blk(256);
    const dim3 tblk(32, 8);

    // transpose decoder weights: Wt[n,k] = W[k,n]
    transpose_kernel<<<dim3(H3D/32,  LATD/32), tblk>>>(Wd1, wt + WT1_OFF, LATD, H3D);
    transpose_kernel<<<dim3(H2D/32,  H3D/32),  tblk>>>(Wd2, wt + WT2_OFF, H3D, H2D);
    transpose_kernel<<<dim3(H1D/32,  H2D/32),  tblk>>>(Wd3, wt + WT3_OFF, H2D, H1D);
    transpose_kernel<<<dim3(INDIM/32, H1D/32), tblk>>>(Wd4, wt + WT4_OFF, H1D, INDIM);

    // encoder (fp32 SIMT — VQ argmin precision depends on z)
    gemm_bias_act<1><<<dim3(H1D/128, 128), blk>>>(x,  We1, be1, h1, M_ROWS, H1D, INDIM);
    gemm_bias_act<1><<<dim3(H2D/128, 128), blk>>>(h1, We2, be2, h2, M_ROWS, H2D, H1D);
    gemm_bias_act<1><<<dim3(H3D/128, 128), blk>>>(h2, We3, be3, h3, M_ROWS, H3D, H2D);
    gemm_bias_act<0><<<dim3(LATD/128, 128), blk>>>(h3, We4, be4, z,  M_ROWS, LATD, H3D);

    // vector quantizer
    vq_kernel<<<512, 256>>>(z, E, e, vqp);

    // decoder (mma.sync 3xTF32)
    gemm_tf32_mma<1><<<dim3(H3D/128, 128), blk>>>(e,  wt + WT1_OFF, bd1, h3,    M_ROWS, H3D, LATD);
    gemm_tf32_mma<1><<<dim3(H2D/128, 128), blk>>>(h3, wt + WT2_OFF, bd2, h2,    M_ROWS, H2D, H3D);
    gemm_tf32_mma<1><<<dim3(H1D/128, 128), blk>>>(h2, wt + WT3_OFF, bd3, h1,    M_ROWS, H1D, H2D);
    gemm_tf32_mma<2><<<dim3(INDIM/128, 128), blk>>>(h1, wt + WT4_OFF, bd4, recon, M_ROWS, INDIM, H1D);

    // losses
    recon_loss_kernel<<<512, 256>>>(recon, x, recp);
    finalize_kernel<<<1, 512>>>(vqp, recp, out + SC_OFF);
}